// round 14
// baseline (speedup 1.0000x reference)
#include <cuda_runtime.h>
#include <cuda_bf16.h>
#include <cstdint>

// Problem constants
#define LSEQ 128
#define BATCH 64
#define EMB 512
#define HID 512          // per direction
#define G4 2048          // 4*HID
#define MROWS 8192       // LSEQ*BATCH
#define NCOLS 4096       // 2 directions * 4H
#define NBLK_REC 128     // recurrence CTAs
#define GRP_CTAS 32      // CTAs per barrier group (dir x batch-half)

// ---------------------------------------------------------------------------
// Scratch (device globals; no allocations allowed)
// ---------------------------------------------------------------------------
__device__ __nv_bfloat16 d_Ahi[(size_t)MROWS * EMB];   // 8 MB emb hi
__device__ __nv_bfloat16 d_Alo[(size_t)MROWS * EMB];   // 8 MB emb lo
__device__ __nv_bfloat16 d_Whi[(size_t)NCOLS * EMB];   // 4 MB Wih (f|b) hi
__device__ __nv_bfloat16 d_Wlo[(size_t)NCOLS * EMB];   // 4 MB Wih (f|b) lo
__device__ float d_Xf [(size_t)MROWS * G4];            // 64 MB
__device__ float d_Xb [(size_t)MROWS * G4];            // 64 MB
__device__ __nv_bfloat16 d_hhi[2 * 2 * BATCH * HID];   // [buf][dir][b][k] hi
__device__ __nv_bfloat16 d_hlo[2 * 2 * BATCH * HID];   // [buf][dir][b][k] lo
// 4 independent barrier groups, 128B-padded slots
__device__ volatile unsigned int d_bar_cnt4[4 * 32];
__device__ volatile unsigned int d_bar_gen4[4 * 32];

// ---------------------------------------------------------------------------
// helpers
// ---------------------------------------------------------------------------
__device__ __forceinline__ uint32_t smem_u32(const void* p) {
    uint32_t a;
    asm("{ .reg .u64 t; cvta.to.shared.u64 t, %1; cvt.u32.u64 %0, t; }"
        : "=r"(a) : "l"(p));
    return a;
}
__device__ __forceinline__ void cp16(uint32_t saddr, const void* g) {
    asm volatile("cp.async.cg.shared.global [%0], [%1], 16;"
                 :: "r"(saddr), "l"(g));
}
#define CP_COMMIT() asm volatile("cp.async.commit_group;" ::: "memory")
#define CP_WAIT(n)  asm volatile("cp.async.wait_group %0;" :: "n"(n) : "memory")

__device__ __forceinline__ void split4(float4 v, uint2& hi, uint2& lo) {
    __nv_bfloat16 hx = __float2bfloat16_rn(v.x);
    __nv_bfloat16 hy = __float2bfloat16_rn(v.y);
    __nv_bfloat16 hz = __float2bfloat16_rn(v.z);
    __nv_bfloat16 hw = __float2bfloat16_rn(v.w);
    __nv_bfloat16 lx = __float2bfloat16_rn(v.x - __bfloat162float(hx));
    __nv_bfloat16 ly = __float2bfloat16_rn(v.y - __bfloat162float(hy));
    __nv_bfloat16 lz = __float2bfloat16_rn(v.z - __bfloat162float(hz));
    __nv_bfloat16 lw = __float2bfloat16_rn(v.w - __bfloat162float(hw));
    hi.x = (uint32_t)__bfloat16_as_ushort(hx) | ((uint32_t)__bfloat16_as_ushort(hy) << 16);
    hi.y = (uint32_t)__bfloat16_as_ushort(hz) | ((uint32_t)__bfloat16_as_ushort(hw) << 16);
    lo.x = (uint32_t)__bfloat16_as_ushort(lx) | ((uint32_t)__bfloat16_as_ushort(ly) << 16);
    lo.y = (uint32_t)__bfloat16_as_ushort(lz) | ((uint32_t)__bfloat16_as_ushort(lw) << 16);
}

__device__ __forceinline__ void mma16816(float* d, const uint32_t* a,
                                         const uint32_t* b) {
    asm volatile(
        "mma.sync.aligned.m16n8k16.row.col.f32.bf16.bf16.f32 "
        "{%0,%1,%2,%3}, {%4,%5,%6,%7}, {%8,%9}, {%0,%1,%2,%3};"
        : "+f"(d[0]), "+f"(d[1]), "+f"(d[2]), "+f"(d[3])
        : "r"(a[0]), "r"(a[1]), "r"(a[2]), "r"(a[3]), "r"(b[0]), "r"(b[1]));
}

// ---------------------------------------------------------------------------
// 1) Embedding gather fused with bf16 hi/lo split
// ---------------------------------------------------------------------------
__global__ void k_embed_cvt(const int* __restrict__ data,
                            const float* __restrict__ table) {
    int i = blockIdx.x * blockDim.x + threadIdx.x;
    if (i >= MROWS * (EMB / 4)) return;
    int m  = i >> 7;
    int e4 = i & 127;
    int w  = data[m];
    float4 v = make_float4(0.f, 0.f, 0.f, 0.f);
    if (w >= 0) v = *(const float4*)(table + (size_t)w * EMB + e4 * 4);
    uint2 hi, lo;
    split4(v, hi, lo);
    *(uint2*)(d_Ahi + (size_t)m * EMB + e4 * 4) = hi;
    *(uint2*)(d_Alo + (size_t)m * EMB + e4 * 4) = lo;
}

// ---------------------------------------------------------------------------
// 1b) Wih stack + split
// ---------------------------------------------------------------------------
__global__ void k_wcvt(const float* __restrict__ Wf, const float* __restrict__ Wb) {
    int i = blockIdx.x * blockDim.x + threadIdx.x;
    if (i >= NCOLS * (EMB / 4)) return;
    int m  = i >> 7;
    int e4 = i & 127;
    const float* src = (m < G4) ? (Wf + (size_t)m * EMB)
                                : (Wb + (size_t)(m - G4) * EMB);
    float4 v = *(const float4*)(src + e4 * 4);
    uint2 hi, lo;
    split4(v, hi, lo);
    *(uint2*)(d_Whi + (size_t)m * EMB + e4 * 4) = hi;
    *(uint2*)(d_Wlo + (size_t)m * EMB + e4 * 4) = lo;
}

// ---------------------------------------------------------------------------
// 2) Split-bf16 mma.sync input GEMM, 2-stage cp.async double buffer.
//    CTA 128M x 128N, 8 warps (4x2), warp tile 32M x 64N, 3 passes.
// ---------------------------------------------------------------------------
#define KC 32
#define SASTR 40
#define GTILE (128 * SASTR)                    // elems per tile per stage
#define SMEM_GEMM (2 * 4 * GTILE * 2)          // 81920 B

__global__ void __launch_bounds__(256)
k_gemm_mma(const float* __restrict__ bihf, const float* __restrict__ bhhf,
           const float* __restrict__ bihb, const float* __restrict__ bhhb) {
    extern __shared__ __nv_bfloat16 sg[];
    const uint32_t smb = smem_u32(sg);

    const int tid  = threadIdx.x;
    const int wid  = tid >> 5, lane = tid & 31;
    const int g    = lane >> 2, t4 = lane & 3;
    const int wm   = wid & 3,  wn = wid >> 2;
    const int n0   = blockIdx.x * 128;
    const int m0   = blockIdx.y * 128;

    const char* gsrc[4] = {
        (const char*)(d_Ahi + (size_t)m0 * EMB),
        (const char*)(d_Alo + (size_t)m0 * EMB),
        (const char*)(d_Whi + (size_t)n0 * EMB),
        (const char*)(d_Wlo + (size_t)n0 * EMB) };

    // issue async loads of chunk ch into stage s
    const int lrow = tid >> 2, lq = tid & 3;   // 64 rows per pass, 2 passes
    auto issue = [&](int ch, int s) {
        const int kb = ch * 64;                // byte offset in 1024 B rows
        const uint32_t sb = smb + (uint32_t)(s * 4 * GTILE * 2);
#pragma unroll
        for (int p = 0; p < 2; p++) {
            int row = lrow + p * 64;
            uint32_t so = sb + (uint32_t)(row * 80 + lq * 16);
            size_t go = (size_t)row * 1024 + kb + lq * 16;
#pragma unroll
            for (int t = 0; t < 4; t++)
                cp16(so + (uint32_t)(t * GTILE * 2), gsrc[t] + go);
        }
    };

    float acc[2][8][4];
#pragma unroll
    for (int mt = 0; mt < 2; mt++)
#pragma unroll
        for (int nt = 0; nt < 8; nt++)
#pragma unroll
            for (int r = 0; r < 4; r++) acc[mt][nt][r] = 0.f;

    issue(0, 0);
    CP_COMMIT();

    for (int ch = 0; ch < EMB / KC; ch++) {
        if (ch + 1 < EMB / KC) issue(ch + 1, (ch + 1) & 1);
        CP_COMMIT();                           // may be empty on last iter
        CP_WAIT(1);                            // stage ch ready
        __syncthreads();

        const __nv_bfloat16* sAh = sg + (size_t)((ch & 1) * 4 + 0) * GTILE;
        const __nv_bfloat16* sAl = sg + (size_t)((ch & 1) * 4 + 1) * GTILE;
        const __nv_bfloat16* sBh = sg + (size_t)((ch & 1) * 4 + 2) * GTILE;
        const __nv_bfloat16* sBl = sg + (size_t)((ch & 1) * 4 + 3) * GTILE;

#pragma unroll
        for (int ks = 0; ks < KC / 16; ks++) {
            const int ko = ks * 16;
            uint32_t ah[2][4], al[2][4];
#pragma unroll
            for (int mt = 0; mt < 2; mt++) {
                int r0 = (wm * 32 + mt * 16 + g) * SASTR + ko + 2 * t4;
                int r1 = (wm * 32 + mt * 16 + g + 8) * SASTR + ko + 2 * t4;
                ah[mt][0] = *(const uint32_t*)&sAh[r0];
                ah[mt][1] = *(const uint32_t*)&sAh[r1];
                ah[mt][2] = *(const uint32_t*)&sAh[r0 + 8];
                ah[mt][3] = *(const uint32_t*)&sAh[r1 + 8];
                al[mt][0] = *(const uint32_t*)&sAl[r0];
                al[mt][1] = *(const uint32_t*)&sAl[r1];
                al[mt][2] = *(const uint32_t*)&sAl[r0 + 8];
                al[mt][3] = *(const uint32_t*)&sAl[r1 + 8];
            }
#pragma unroll
            for (int nt = 0; nt < 8; nt++) {
                int rb = (wn * 64 + nt * 8 + g) * SASTR + ko + 2 * t4;
                uint32_t bh[2], bl[2];
                bh[0] = *(const uint32_t*)&sBh[rb];
                bh[1] = *(const uint32_t*)&sBh[rb + 8];
                bl[0] = *(const uint32_t*)&sBl[rb];
                bl[1] = *(const uint32_t*)&sBl[rb + 8];
                mma16816(acc[0][nt], ah[0], bh);
                mma16816(acc[1][nt], ah[1], bh);
                mma16816(acc[0][nt], ah[0], bl);
                mma16816(acc[1][nt], ah[1], bl);
                mma16816(acc[0][nt], al[0], bh);
                mma16816(acc[1][nt], al[1], bh);
            }
        }
        __syncthreads();                       // stage reusable next-next iter
    }

    const bool fwd = (n0 < G4);
    const int nb = fwd ? n0 : (n0 - G4);
    const float* bi = fwd ? bihf : bihb;
    const float* bh = fwd ? bhhf : bhhb;
    float* dstbase = fwd ? d_Xf : d_Xb;
#pragma unroll
    for (int nt = 0; nt < 8; nt++) {
        int n = nb + wn * 64 + nt * 8 + 2 * t4;
        float b0 = bi[n] + bh[n];
        float b1 = bi[n + 1] + bh[n + 1];
#pragma unroll
        for (int mt = 0; mt < 2; mt++) {
            int mr0 = m0 + wm * 32 + mt * 16 + g;
            float2 v0 = make_float2(acc[mt][nt][0] + b0, acc[mt][nt][1] + b1);
            float2 v1 = make_float2(acc[mt][nt][2] + b0, acc[mt][nt][3] + b1);
            *(float2*)(dstbase + (size_t)mr0 * G4 + n) = v0;
            *(float2*)(dstbase + (size_t)(mr0 + 8) * G4 + n) = v1;
        }
    }
}

// ---------------------------------------------------------------------------
// 3) Init: zero h split buffers, reset all barrier groups.
// ---------------------------------------------------------------------------
__global__ void k_init() {
    int i = blockIdx.x * blockDim.x + threadIdx.x;
    if (i < 2 * 2 * BATCH * HID) {
        d_hhi[i] = __float2bfloat16(0.f);
        d_hlo[i] = __float2bfloat16(0.f);
    }
    if (i < 4 * 32) { d_bar_cnt4[i] = 0u; d_bar_gen4[i] = 0u; }
}

// ---------------------------------------------------------------------------
// 4) Persistent recurrence, split-bf16 mma.sync.
//    bid = dir*64 + bh*32 + u  ->  barrier group = bid>>5 (32 CTAs).
// ---------------------------------------------------------------------------
#define RSTR 520
#define RS_WH 0
#define RS_WL (RS_WH + 64 * RSTR)
#define RS_HH (RS_WL + 64 * RSTR)
#define RS_HL (RS_HH + 32 * RSTR)
#define RS_END (RS_HL + 32 * RSTR)
#define SMEM_RECUR (RS_END * 2 + (32 * 68 + 32 * 16) * 4)

__global__ void __launch_bounds__(256, 1)
k_recur_mma(const float* __restrict__ Whf, const float* __restrict__ Whb,
            const float* __restrict__ mask, float* __restrict__ out) {
    extern __shared__ __nv_bfloat16 smr[];
    __nv_bfloat16* sWh = smr + RS_WH;
    __nv_bfloat16* sWl = smr + RS_WL;
    __nv_bfloat16* sHh = smr + RS_HH;
    __nv_bfloat16* sHl = smr + RS_HL;
    float* Cs  = (float*)(smr + RS_END);        // [32][68]
    float* c_s = Cs + 32 * 68;                  // [32][16]
    const uint32_t smbHH = smem_u32(sHh);
    const uint32_t smbHL = smem_u32(sHl);

    const int tid  = threadIdx.x;
    const int wid  = tid >> 5, lane = tid & 31;
    const int g    = lane >> 2, t4 = lane & 3;
    const int wm   = wid & 1,  wn = wid >> 1;   // 2m x 4n warps
    const int dir  = blockIdx.x >> 6;
    const int grp  = blockIdx.x >> 5;           // 4 groups of 32
    const int b0g  = ((blockIdx.x >> 5) & 1) * 32;
    const int u0   = (blockIdx.x & 31) * 16;
    const float* Wsrc = dir ? Whb : Whf;
    const float* X    = dir ? d_Xb : d_Xf;

    // One-time: load + split Whh slice. smem col n = gate*16 + uu.
    for (int it = 0; it < 32; it++) {
        int n    = it * 2 + (tid >> 7);
        int k4   = (tid & 127) * 4;
        int grow = (n >> 4) * HID + u0 + (n & 15);
        float4 v = *(const float4*)(Wsrc + (size_t)grow * HID + k4);
        uint2 hi, lo;
        split4(v, hi, lo);
        *(uint2*)&sWh[n * RSTR + k4] = hi;
        *(uint2*)&sWl[n * RSTR + k4] = lo;
    }
    for (int i = tid; i < 32 * 16; i += 256) c_s[i] = 0.f;
    __syncthreads();

    // epilogue item coords (2 per thread), fixed across steps
    const int eb0 = tid >> 4,        euu = tid & 15;        // item 0
    const int eb1 = (tid + 256) >> 4;                       // item 1 (same uu)

    for (int step = 0; step < LSEQ; step++) {
        const int tcur = dir ? (LSEQ - 1 - step) : step;
        const int cur = step & 1, nxt = cur ^ 1;
        const __nv_bfloat16* hh = d_hhi + ((size_t)(cur * 2 + dir) * BATCH + b0g) * HID;
        const __nv_bfloat16* hl = d_hlo + ((size_t)(cur * 2 + dir) * BATCH + b0g) * HID;

        // stage h tile [32][512] hi+lo via cp.async
#pragma unroll
        for (int i = tid; i < 2048; i += 256) {
            int row = i >> 6, k8 = (i & 63) * 8;
            uint32_t so = (uint32_t)(row * RSTR + k8) * 2;
            const __nv_bfloat16* gp = hh + (size_t)row * HID + k8;
            cp16(smbHH + so, gp);
            cp16(smbHL + so, hl + (size_t)row * HID + k8);
        }
        CP_COMMIT();

        // prefetch X gates + mask while the cp.asyncs fly
        size_t xb0 = ((size_t)(tcur * BATCH + b0g + eb0)) * G4 + u0 + euu;
        size_t xb1 = ((size_t)(tcur * BATCH + b0g + eb1)) * G4 + u0 + euu;
        float xi0 = X[xb0],        xi1 = X[xb1];
        float xf0 = X[xb0 + 512],  xf1 = X[xb1 + 512];
        float xg0 = X[xb0 + 1024], xg1 = X[xb1 + 1024];
        float xo0 = X[xb0 + 1536], xo1 = X[xb1 + 1536];
        float m0 = mask[tcur * BATCH + b0g + eb0];
        float m1 = mask[tcur * BATCH + b0g + eb1];

        CP_WAIT(0);
        __syncthreads();

        float acc[2][4];
#pragma unroll
        for (int nt = 0; nt < 2; nt++)
#pragma unroll
            for (int r = 0; r < 4; r++) acc[nt][r] = 0.f;

#pragma unroll 4
        for (int ks = 0; ks < 32; ks++) {
            const int ko = ks * 16;
            uint32_t ah[4], al[4];
            {
                int r0 = (wm * 16 + g) * RSTR + ko + 2 * t4;
                int r1 = r0 + 8 * RSTR;
                ah[0] = *(const uint32_t*)&sHh[r0];
                ah[1] = *(const uint32_t*)&sHh[r1];
                ah[2] = *(const uint32_t*)&sHh[r0 + 8];
                ah[3] = *(const uint32_t*)&sHh[r1 + 8];
                al[0] = *(const uint32_t*)&sHl[r0];
                al[1] = *(const uint32_t*)&sHl[r1];
                al[2] = *(const uint32_t*)&sHl[r0 + 8];
                al[3] = *(const uint32_t*)&sHl[r1 + 8];
            }
            uint32_t bh0[2], bl0[2], bh1[2], bl1[2];
            {
                int rb0 = (wn * 16 + g) * RSTR + ko + 2 * t4;
                int rb1 = rb0 + 8 * RSTR;
                bh0[0] = *(const uint32_t*)&sWh[rb0];
                bh0[1] = *(const uint32_t*)&sWh[rb0 + 8];
                bl0[0] = *(const uint32_t*)&sWl[rb0];
                bl0[1] = *(const uint32_t*)&sWl[rb0 + 8];
                bh1[0] = *(const uint32_t*)&sWh[rb1];
                bh1[1] = *(const uint32_t*)&sWh[rb1 + 8];
                bl1[0] = *(const uint32_t*)&sWl[rb1];
                bl1[1] = *(const uint32_t*)&sWl[rb1 + 8];
            }
            mma16816(acc[0], ah, bh0);
            mma16816(acc[1], ah, bh1);
            mma16816(acc[0], ah, bl0);
            mma16816(acc[1], ah, bl1);
            mma16816(acc[0], al, bh0);
            mma16816(acc[1], al, bh1);
        }

#pragma unroll
        for (int nt = 0; nt < 2; nt++) {
            int col = wn * 16 + nt * 8 + 2 * t4;
            int r0 = (wm * 16 + g) * 68 + col;
            Cs[r0]      = acc[nt][0];
            Cs[r0 + 1]  = acc[nt][1];
            Cs[r0 + 8 * 68]     = acc[nt][2];
            Cs[r0 + 8 * 68 + 1] = acc[nt][3];
        }
        __syncthreads();

        // epilogue (2 items, X/mask already in regs)
#pragma unroll
        for (int p = 0; p < 2; p++) {
            int b  = p ? eb1 : eb0;
            float gi = Cs[b * 68 + euu]      + (p ? xi1 : xi0);
            float gf = Cs[b * 68 + 16 + euu] + (p ? xf1 : xf0);
            float gg = Cs[b * 68 + 32 + euu] + (p ? xg1 : xg0);
            float go = Cs[b * 68 + 48 + euu] + (p ? xo1 : xo0);
            float si = 1.f / (1.f + __expf(-gi));
            float sf = 1.f / (1.f + __expf(-gf));
            float so = 1.f / (1.f + __expf(-go));
            float c  = sf * c_s[b * 16 + euu] + si * tanhf(gg);
            float h  = so * tanhf(c);
            float m  = p ? m1 : m0;
            c *= m; h *= m;
            c_s[b * 16 + euu] = c;
            out[((size_t)(tcur * BATCH + b0g + b)) * 1024 + dir * HID + u0 + euu] = h;
            __nv_bfloat16 hbi = __float2bfloat16_rn(h);
            __nv_bfloat16 hbl = __float2bfloat16_rn(h - __bfloat162float(hbi));
            size_t hidx = ((size_t)(nxt * 2 + dir) * BATCH + b0g + b) * HID + u0 + euu;
            d_hhi[hidx] = hbi;
            d_hlo[hidx] = hbl;
        }

        // ---- group barrier (32 CTAs sharing (dir, batch-half)) ----
        __threadfence();
        __syncthreads();
        if (tid == 0) {
            const unsigned int target = (unsigned)(step + 1);
            volatile unsigned int* cnt = &d_bar_cnt4[grp * 32];
            volatile unsigned int* gen = &d_bar_gen4[grp * 32];
            unsigned int arrived =
                atomicAdd((unsigned int*)cnt, 1u) + 1u;
            if (arrived == (unsigned)GRP_CTAS * target) {
                __threadfence();
                atomicAdd((unsigned int*)gen, 1u);
            } else {
                unsigned ns = 32;
                while (*gen < target) {
                    __nanosleep(ns);
                    if (ns < 256) ns <<= 1;
                }
            }
        }
        __syncthreads();
        __threadfence();
    }
}

// ---------------------------------------------------------------------------
// Launch
// ---------------------------------------------------------------------------
extern "C" void kernel_launch(void* const* d_in, const int* in_sizes, int n_in,
                              void* d_out, int out_size) {
    const int*   data  = (const int*)  d_in[0];
    const float* mask  = (const float*)d_in[1];
    const float* table = (const float*)d_in[2];
    const float* Wih_f = (const float*)d_in[3];
    const float* Whh_f = (const float*)d_in[4];
    const float* bih_f = (const float*)d_in[5];
    const float* bhh_f = (const float*)d_in[6];
    const float* Wih_b = (const float*)d_in[7];
    const float* Whh_b = (const float*)d_in[8];
    const float* bih_b = (const float*)d_in[9];
    const float* bhh_b = (const float*)d_in[10];
    float* out = (float*)d_out;

    (void)in_sizes; (void)n_in; (void)out_size;

    cudaFuncSetAttribute(k_recur_mma,
                         cudaFuncAttributeMaxDynamicSharedMemorySize, SMEM_RECUR);
    cudaFuncSetAttribute(k_gemm_mma,
                         cudaFuncAttributeMaxDynamicSharedMemorySize, SMEM_GEMM);

    k_embed_cvt<<<(MROWS * (EMB / 4) + 255) / 256, 256>>>(data, table);
    k_wcvt<<<(NCOLS * (EMB / 4) + 255) / 256, 256>>>(Wih_f, Wih_b);

    dim3 ggrid(NCOLS / 128, MROWS / 128);   // 32 x 64
    k_gemm_mma<<<ggrid, 256, SMEM_GEMM>>>(bih_f, bhh_f, bih_b, bhh_b);

    k_init<<<512, 256>>>();

    k_recur_mma<<<NBLK_REC, 256, SMEM_RECUR>>>(Whh_f, Whh_b, mask, out);
}

// round 15
// speedup vs baseline: 1.3947x; 1.3947x over previous
#include <cuda_runtime.h>
#include <cuda_bf16.h>
#include <cstdint>

// Problem constants
#define LSEQ 128
#define BATCH 64
#define EMB 512
#define HID 512          // per direction
#define G4 2048          // 4*HID
#define MROWS 8192       // LSEQ*BATCH
#define NCOLS 4096       // 2 directions * 4H
#define NBLK_REC 128     // recurrence CTAs
#define GRP_CTAS 32      // CTAs per barrier group (dir x batch-half)

// ---------------------------------------------------------------------------
// Scratch (device globals; no allocations allowed)
// ---------------------------------------------------------------------------
__device__ __nv_bfloat16 d_Ahi[(size_t)MROWS * EMB];   // 8 MB emb hi
__device__ __nv_bfloat16 d_Alo[(size_t)MROWS * EMB];   // 8 MB emb lo
__device__ __nv_bfloat16 d_Whi[(size_t)NCOLS * EMB];   // 4 MB Wih (f|b) hi
__device__ __nv_bfloat16 d_Wlo[(size_t)NCOLS * EMB];   // 4 MB Wih (f|b) lo
__device__ float d_Xf [(size_t)MROWS * G4];            // 64 MB
__device__ float d_Xb [(size_t)MROWS * G4];            // 64 MB
__device__ __nv_bfloat16 d_hhi[2 * 2 * BATCH * HID];   // [buf][dir][b][k] hi
__device__ __nv_bfloat16 d_hlo[2 * 2 * BATCH * HID];   // [buf][dir][b][k] lo
// 4 independent barrier groups, 128B-padded slots
__device__ volatile unsigned int d_bar_cnt4[4 * 32];
__device__ volatile unsigned int d_bar_gen4[4 * 32];

// ---------------------------------------------------------------------------
// bf16 hi/lo split helpers
// ---------------------------------------------------------------------------
__device__ __forceinline__ void split4(float4 v, uint2& hi, uint2& lo) {
    __nv_bfloat16 hx = __float2bfloat16_rn(v.x);
    __nv_bfloat16 hy = __float2bfloat16_rn(v.y);
    __nv_bfloat16 hz = __float2bfloat16_rn(v.z);
    __nv_bfloat16 hw = __float2bfloat16_rn(v.w);
    __nv_bfloat16 lx = __float2bfloat16_rn(v.x - __bfloat162float(hx));
    __nv_bfloat16 ly = __float2bfloat16_rn(v.y - __bfloat162float(hy));
    __nv_bfloat16 lz = __float2bfloat16_rn(v.z - __bfloat162float(hz));
    __nv_bfloat16 lw = __float2bfloat16_rn(v.w - __bfloat162float(hw));
    hi.x = (uint32_t)__bfloat16_as_ushort(hx) | ((uint32_t)__bfloat16_as_ushort(hy) << 16);
    hi.y = (uint32_t)__bfloat16_as_ushort(hz) | ((uint32_t)__bfloat16_as_ushort(hw) << 16);
    lo.x = (uint32_t)__bfloat16_as_ushort(lx) | ((uint32_t)__bfloat16_as_ushort(ly) << 16);
    lo.y = (uint32_t)__bfloat16_as_ushort(lz) | ((uint32_t)__bfloat16_as_ushort(lw) << 16);
}

__device__ __forceinline__ void mma16816(float* d, const uint32_t* a,
                                         const uint32_t* b) {
    asm volatile(
        "mma.sync.aligned.m16n8k16.row.col.f32.bf16.bf16.f32 "
        "{%0,%1,%2,%3}, {%4,%5,%6,%7}, {%8,%9}, {%0,%1,%2,%3};"
        : "+f"(d[0]), "+f"(d[1]), "+f"(d[2]), "+f"(d[3])
        : "r"(a[0]), "r"(a[1]), "r"(a[2]), "r"(a[3]), "r"(b[0]), "r"(b[1]));
}

// ---------------------------------------------------------------------------
// 1) Embedding gather fused with bf16 hi/lo split
// ---------------------------------------------------------------------------
__global__ void k_embed_cvt(const int* __restrict__ data,
                            const float* __restrict__ table) {
    int i = blockIdx.x * blockDim.x + threadIdx.x;
    if (i >= MROWS * (EMB / 4)) return;
    int m  = i >> 7;
    int e4 = i & 127;
    int w  = data[m];
    float4 v = make_float4(0.f, 0.f, 0.f, 0.f);
    if (w >= 0) v = *(const float4*)(table + (size_t)w * EMB + e4 * 4);
    uint2 hi, lo;
    split4(v, hi, lo);
    *(uint2*)(d_Ahi + (size_t)m * EMB + e4 * 4) = hi;
    *(uint2*)(d_Alo + (size_t)m * EMB + e4 * 4) = lo;
}

// ---------------------------------------------------------------------------
// 1b) Wih stack + split
// ---------------------------------------------------------------------------
__global__ void k_wcvt(const float* __restrict__ Wf, const float* __restrict__ Wb) {
    int i = blockIdx.x * blockDim.x + threadIdx.x;
    if (i >= NCOLS * (EMB / 4)) return;
    int m  = i >> 7;
    int e4 = i & 127;
    const float* src = (m < G4) ? (Wf + (size_t)m * EMB)
                                : (Wb + (size_t)(m - G4) * EMB);
    float4 v = *(const float4*)(src + e4 * 4);
    uint2 hi, lo;
    split4(v, hi, lo);
    *(uint2*)(d_Whi + (size_t)m * EMB + e4 * 4) = hi;
    *(uint2*)(d_Wlo + (size_t)m * EMB + e4 * 4) = lo;
}

// ---------------------------------------------------------------------------
// 2) Split-bf16 mma.sync input GEMM — EXACT R13 version (40 KB static smem,
//    2 CTAs/SM; part of the measured 1487 us config).
// ---------------------------------------------------------------------------
#define KC 32
#define SASTR 40

__global__ void __launch_bounds__(256, 1)
k_gemm_mma(const float* __restrict__ bihf, const float* __restrict__ bhhf,
           const float* __restrict__ bihb, const float* __restrict__ bhhb) {
    __shared__ __nv_bfloat16 sAh[128 * SASTR];
    __shared__ __nv_bfloat16 sAl[128 * SASTR];
    __shared__ __nv_bfloat16 sBh[128 * SASTR];
    __shared__ __nv_bfloat16 sBl[128 * SASTR];

    const int tid  = threadIdx.x;
    const int wid  = tid >> 5, lane = tid & 31;
    const int g    = lane >> 2, t4 = lane & 3;
    const int wm   = wid & 3,  wn = wid >> 2;
    const int n0   = blockIdx.x * 128;
    const int m0   = blockIdx.y * 128;

    const char* Ah = (const char*)(d_Ahi + (size_t)m0 * EMB);
    const char* Al = (const char*)(d_Alo + (size_t)m0 * EMB);
    const char* Bh = (const char*)(d_Whi + (size_t)n0 * EMB);
    const char* Bl = (const char*)(d_Wlo + (size_t)n0 * EMB);

    float acc[2][8][4];
#pragma unroll
    for (int mt = 0; mt < 2; mt++)
#pragma unroll
        for (int nt = 0; nt < 8; nt++)
#pragma unroll
            for (int r = 0; r < 4; r++) acc[mt][nt][r] = 0.f;

    for (int ch = 0; ch < EMB / KC; ch++) {
        const int kb = ch * KC * 2;
        __syncthreads();
#pragma unroll
        for (int i = tid; i < 512; i += 256) {
            int row = i >> 2, q = i & 3;
            size_t gsrc = (size_t)row * 1024 + kb + q * 16;
            int sdst = row * SASTR + q * 8;
            *(uint4*)&sAh[sdst] = *(const uint4*)(Ah + gsrc);
            *(uint4*)&sAl[sdst] = *(const uint4*)(Al + gsrc);
            *(uint4*)&sBh[sdst] = *(const uint4*)(Bh + gsrc);
            *(uint4*)&sBl[sdst] = *(const uint4*)(Bl + gsrc);
        }
        __syncthreads();

#pragma unroll
        for (int ks = 0; ks < KC / 16; ks++) {
            const int ko = ks * 16;
            uint32_t ah[2][4], al[2][4];
#pragma unroll
            for (int mt = 0; mt < 2; mt++) {
                int r0 = (wm * 32 + mt * 16 + g) * SASTR + ko + 2 * t4;
                int r1 = (wm * 32 + mt * 16 + g + 8) * SASTR + ko + 2 * t4;
                ah[mt][0] = *(const uint32_t*)&sAh[r0];
                ah[mt][1] = *(const uint32_t*)&sAh[r1];
                ah[mt][2] = *(const uint32_t*)&sAh[r0 + 8];
                ah[mt][3] = *(const uint32_t*)&sAh[r1 + 8];
                al[mt][0] = *(const uint32_t*)&sAl[r0];
                al[mt][1] = *(const uint32_t*)&sAl[r1];
                al[mt][2] = *(const uint32_t*)&sAl[r0 + 8];
                al[mt][3] = *(const uint32_t*)&sAl[r1 + 8];
            }
#pragma unroll
            for (int nt = 0; nt < 8; nt++) {
                int rb = (wn * 64 + nt * 8 + g) * SASTR + ko + 2 * t4;
                uint32_t bh[2], bl[2];
                bh[0] = *(const uint32_t*)&sBh[rb];
                bh[1] = *(const uint32_t*)&sBh[rb + 8];
                bl[0] = *(const uint32_t*)&sBl[rb];
                bl[1] = *(const uint32_t*)&sBl[rb + 8];
                mma16816(acc[0][nt], ah[0], bh);
                mma16816(acc[1][nt], ah[1], bh);
                mma16816(acc[0][nt], ah[0], bl);
                mma16816(acc[1][nt], ah[1], bl);
                mma16816(acc[0][nt], al[0], bh);
                mma16816(acc[1][nt], al[1], bh);
            }
        }
    }

    const bool fwd = (n0 < G4);
    const int nb = fwd ? n0 : (n0 - G4);
    const float* bi = fwd ? bihf : bihb;
    const float* bh = fwd ? bhhf : bhhb;
    float* dstbase = fwd ? d_Xf : d_Xb;
#pragma unroll
    for (int nt = 0; nt < 8; nt++) {
        int n = nb + wn * 64 + nt * 8 + 2 * t4;
        float b0 = bi[n] + bh[n];
        float b1 = bi[n + 1] + bh[n + 1];
#pragma unroll
        for (int mt = 0; mt < 2; mt++) {
            int mr0 = m0 + wm * 32 + mt * 16 + g;
            float2 v0 = make_float2(acc[mt][nt][0] + b0, acc[mt][nt][1] + b1);
            float2 v1 = make_float2(acc[mt][nt][2] + b0, acc[mt][nt][3] + b1);
            *(float2*)(dstbase + (size_t)mr0 * G4 + n) = v0;
            *(float2*)(dstbase + (size_t)(mr0 + 8) * G4 + n) = v1;
        }
    }
}

// ---------------------------------------------------------------------------
// 3) Init: zero h split buffers, reset all barrier groups.
// ---------------------------------------------------------------------------
__global__ void k_init() {
    int i = blockIdx.x * blockDim.x + threadIdx.x;
    if (i < 2 * 2 * BATCH * HID) {
        d_hhi[i] = __float2bfloat16(0.f);
        d_hlo[i] = __float2bfloat16(0.f);
    }
    if (i < 4 * 32) { d_bar_cnt4[i] = 0u; d_bar_gen4[i] = 0u; }
}

// ---------------------------------------------------------------------------
// 4) Persistent recurrence, split-bf16 mma.sync (R13 base).
//    Changes vs R13: (a) 4 independent 32-CTA barrier groups,
//                    (b) X-gate/mask register prefetch at step start.
//    Staging uses plain LDG->STS exactly as R13 (no cp.async).
// ---------------------------------------------------------------------------
#define RSTR 520
#define RS_WH 0
#define RS_WL (RS_WH + 64 * RSTR)
#define RS_HH (RS_WL + 64 * RSTR)
#define RS_HL (RS_HH + 32 * RSTR)
#define RS_END (RS_HL + 32 * RSTR)
#define SMEM_RECUR (RS_END * 2 + (32 * 68 + 32 * 16) * 4)

__global__ void __launch_bounds__(256, 1)
k_recur_mma(const float* __restrict__ Whf, const float* __restrict__ Whb,
            const float* __restrict__ mask, float* __restrict__ out) {
    extern __shared__ __nv_bfloat16 smr[];
    __nv_bfloat16* sWh = smr + RS_WH;
    __nv_bfloat16* sWl = smr + RS_WL;
    __nv_bfloat16* sHh = smr + RS_HH;
    __nv_bfloat16* sHl = smr + RS_HL;
    float* Cs  = (float*)(smr + RS_END);        // [32][68]
    float* c_s = Cs + 32 * 68;                  // [32][16]

    const int tid  = threadIdx.x;
    const int wid  = tid >> 5, lane = tid & 31;
    const int g    = lane >> 2, t4 = lane & 3;
    const int wm   = wid & 1,  wn = wid >> 1;   // 2m x 4n warps
    const int dir  = blockIdx.x >> 6;
    const int grp  = blockIdx.x >> 5;           // 4 groups of 32 CTAs
    const int b0g  = ((blockIdx.x >> 5) & 1) * 32;
    const int u0   = (blockIdx.x & 31) * 16;
    const float* Wsrc = dir ? Whb : Whf;
    const float* X    = dir ? d_Xb : d_Xf;

    // One-time: load + split Whh slice. smem col n = gate*16 + uu.
    for (int it = 0; it < 32; it++) {
        int n    = it * 2 + (tid >> 7);
        int k4   = (tid & 127) * 4;
        int grow = (n >> 4) * HID + u0 + (n & 15);
        float4 v = *(const float4*)(Wsrc + (size_t)grow * HID + k4);
        uint2 hi, lo;
        split4(v, hi, lo);
        *(uint2*)&sWh[n * RSTR + k4] = hi;
        *(uint2*)&sWl[n * RSTR + k4] = lo;
    }
    for (int i = tid; i < 32 * 16; i += 256) c_s[i] = 0.f;
    __syncthreads();

    // epilogue item coords (2 per thread), fixed across steps
    const int eb0 = tid >> 4,        euu = tid & 15;
    const int eb1 = (tid + 256) >> 4;

    for (int step = 0; step < LSEQ; step++) {
        const int tcur = dir ? (LSEQ - 1 - step) : step;
        const int cur = step & 1, nxt = cur ^ 1;
        const __nv_bfloat16* hh = d_hhi + ((size_t)(cur * 2 + dir) * BATCH + b0g) * HID;
        const __nv_bfloat16* hl = d_hlo + ((size_t)(cur * 2 + dir) * BATCH + b0g) * HID;

        // prefetch X gates + mask (independent of h) — hides gmem latency
        size_t xb0 = ((size_t)(tcur * BATCH + b0g + eb0)) * G4 + u0 + euu;
        size_t xb1 = ((size_t)(tcur * BATCH + b0g + eb1)) * G4 + u0 + euu;
        float xi0 = X[xb0],        xi1 = X[xb1];
        float xf0 = X[xb0 + 512],  xf1 = X[xb1 + 512];
        float xg0 = X[xb0 + 1024], xg1 = X[xb1 + 1024];
        float xo0 = X[xb0 + 1536], xo1 = X[xb1 + 1536];
        float m0 = mask[tcur * BATCH + b0g + eb0];
        float m1 = mask[tcur * BATCH + b0g + eb1];

        // stage h tile [32][512] hi+lo into smem (R13 pattern)
#pragma unroll
        for (int i = tid; i < 2048; i += 256) {
            int row = i >> 6, k8 = (i & 63) * 8;
            *(uint4*)&sHh[row * RSTR + k8] = *(const uint4*)(hh + (size_t)row * HID + k8);
            *(uint4*)&sHl[row * RSTR + k8] = *(const uint4*)(hl + (size_t)row * HID + k8);
        }
        __syncthreads();

        float acc[2][4];
#pragma unroll
        for (int nt = 0; nt < 2; nt++)
#pragma unroll
            for (int r = 0; r < 4; r++) acc[nt][r] = 0.f;

#pragma unroll 4
        for (int ks = 0; ks < 32; ks++) {
            const int ko = ks * 16;
            uint32_t ah[4], al[4];
            {
                int r0 = (wm * 16 + g) * RSTR + ko + 2 * t4;
                int r1 = r0 + 8 * RSTR;
                ah[0] = *(const uint32_t*)&sHh[r0];
                ah[1] = *(const uint32_t*)&sHh[r1];
                ah[2] = *(const uint32_t*)&sHh[r0 + 8];
                ah[3] = *(const uint32_t*)&sHh[r1 + 8];
                al[0] = *(const uint32_t*)&sHl[r0];
                al[1] = *(const uint32_t*)&sHl[r1];
                al[2] = *(const uint32_t*)&sHl[r0 + 8];
                al[3] = *(const uint32_t*)&sHl[r1 + 8];
            }
            uint32_t bh0[2], bl0[2], bh1[2], bl1[2];
            {
                int rb0 = (wn * 16 + g) * RSTR + ko + 2 * t4;
                int rb1 = rb0 + 8 * RSTR;
                bh0[0] = *(const uint32_t*)&sWh[rb0];
                bh0[1] = *(const uint32_t*)&sWh[rb0 + 8];
                bl0[0] = *(const uint32_t*)&sWl[rb0];
                bl0[1] = *(const uint32_t*)&sWl[rb0 + 8];
                bh1[0] = *(const uint32_t*)&sWh[rb1];
                bh1[1] = *(const uint32_t*)&sWh[rb1 + 8];
                bl1[0] = *(const uint32_t*)&sWl[rb1];
                bl1[1] = *(const uint32_t*)&sWl[rb1 + 8];
            }
            mma16816(acc[0], ah, bh0);
            mma16816(acc[1], ah, bh1);
            mma16816(acc[0], ah, bl0);
            mma16816(acc[1], ah, bl1);
            mma16816(acc[0], al, bh0);
            mma16816(acc[1], al, bh1);
        }

#pragma unroll
        for (int nt = 0; nt < 2; nt++) {
            int col = wn * 16 + nt * 8 + 2 * t4;
            int r0 = (wm * 16 + g) * 68 + col;
            Cs[r0]      = acc[nt][0];
            Cs[r0 + 1]  = acc[nt][1];
            Cs[r0 + 8 * 68]     = acc[nt][2];
            Cs[r0 + 8 * 68 + 1] = acc[nt][3];
        }
        __syncthreads();

        // epilogue (2 items; X/mask already in registers)
#pragma unroll
        for (int p = 0; p < 2; p++) {
            int b  = p ? eb1 : eb0;
            float gi = Cs[b * 68 + euu]      + (p ? xi1 : xi0);
            float gf = Cs[b * 68 + 16 + euu] + (p ? xf1 : xf0);
            float gg = Cs[b * 68 + 32 + euu] + (p ? xg1 : xg0);
            float go = Cs[b * 68 + 48 + euu] + (p ? xo1 : xo0);
            float si = 1.f / (1.f + __expf(-gi));
            float sf = 1.f / (1.f + __expf(-gf));
            float so = 1.f / (1.f + __expf(-go));
            float c  = sf * c_s[b * 16 + euu] + si * tanhf(gg);
            float h  = so * tanhf(c);
            float m  = p ? m1 : m0;
            c *= m; h *= m;
            c_s[b * 16 + euu] = c;
            out[((size_t)(tcur * BATCH + b0g + b)) * 1024 + dir * HID + u0 + euu] = h;
            __nv_bfloat16 hbi = __float2bfloat16_rn(h);
            __nv_bfloat16 hbl = __float2bfloat16_rn(h - __bfloat162float(hbi));
            size_t hidx = ((size_t)(nxt * 2 + dir) * BATCH + b0g + b) * HID + u0 + euu;
            d_hhi[hidx] = hbi;
            d_hlo[hidx] = hbl;
        }

        // ---- group barrier (32 CTAs sharing (dir, batch-half)) ----
        __threadfence();
        __syncthreads();
        if (tid == 0) {
            const unsigned int target = (unsigned)(step + 1);
            volatile unsigned int* cnt = &d_bar_cnt4[grp * 32];
            volatile unsigned int* gen = &d_bar_gen4[grp * 32];
            unsigned int arrived =
                atomicAdd((unsigned int*)cnt, 1u) + 1u;
            if (arrived == (unsigned)GRP_CTAS * target) {
                __threadfence();
                atomicAdd((unsigned int*)gen, 1u);
            } else {
                unsigned ns = 32;
                while (*gen < target) {
                    __nanosleep(ns);
                    if (ns < 256) ns <<= 1;
                }
            }
        }
        __syncthreads();
        __threadfence();
    }
}

// ---------------------------------------------------------------------------
// Launch
// ---------------------------------------------------------------------------
extern "C" void kernel_launch(void* const* d_in, const int* in_sizes, int n_in,
                              void* d_out, int out_size) {
    const int*   data  = (const int*)  d_in[0];
    const float* mask  = (const float*)d_in[1];
    const float* table = (const float*)d_in[2];
    const float* Wih_f = (const float*)d_in[3];
    const float* Whh_f = (const float*)d_in[4];
    const float* bih_f = (const float*)d_in[5];
    const float* bhh_f = (const float*)d_in[6];
    const float* Wih_b = (const float*)d_in[7];
    const float* Whh_b = (const float*)d_in[8];
    const float* bih_b = (const float*)d_in[9];
    const float* bhh_b = (const float*)d_in[10];
    float* out = (float*)d_out;

    (void)in_sizes; (void)n_in; (void)out_size;

    cudaFuncSetAttribute(k_recur_mma,
                         cudaFuncAttributeMaxDynamicSharedMemorySize, SMEM_RECUR);

    k_embed_cvt<<<(MROWS * (EMB / 4) + 255) / 256, 256>>>(data, table);
    k_wcvt<<<(NCOLS * (EMB / 4) + 255) / 256, 256>>>(Wih_f, Wih_b);

    dim3 ggrid(NCOLS / 128, MROWS / 128);   // 32 x 64
    k_gemm_mma<<<ggrid, 256>>>(bih_f, bhh_f, bih_b, bhh_b);

    k_init<<<512, 256>>>();

    k_recur_mma<<<NBLK_REC, 256, SMEM_RECUR>>>(Whh_f, Whh_b, mask, out);
}